// round 3
// baseline (speedup 1.0000x reference)
#include <cuda_runtime.h>
#include <cstdint>
#include <math.h>

// Problem constants
#define BB 4
#define TT 8192
#define HH 16
#define DD 64
#define CC 128                 // chunk length
#define NC (TT/CC)             // 64 chunks per sequence
#define BHN (BB*HH)            // 64 (b,h) pairs
#define NCHUNKS (BHN*NC)       // 4096 total chunks
#define EPSV 1e-6f

// Scratch: per-chunk KV matrices (later converted in-place to exclusive prefix = S_prev)
__device__ float g_M[(size_t)NCHUNKS * DD * DD];   // 64 MB
__device__ float g_z[(size_t)NCHUNKS * DD];        // 1 MB

__device__ __forceinline__ float phi_f(float x) {
    // elu(x)+1 : x>0 -> x+1 ; x<=0 -> exp(x)
    return x > 0.f ? x + 1.f : expf(x);
}

__device__ __forceinline__ float tf32r(float x) {
    uint32_t u;
    asm("cvt.rna.tf32.f32 %0, %1;" : "=r"(u) : "f"(x));
    return __uint_as_float(u);
}

__device__ __forceinline__ void mma8(float* d, const uint32_t* a, const uint32_t* b) {
    asm volatile(
        "mma.sync.aligned.m16n8k8.row.col.f32.tf32.tf32.f32 "
        "{%0,%1,%2,%3}, {%4,%5,%6,%7}, {%8,%9}, {%0,%1,%2,%3};"
        : "+f"(d[0]), "+f"(d[1]), "+f"(d[2]), "+f"(d[3])
        : "r"(a[0]), "r"(a[1]), "r"(a[2]), "r"(a[3]), "r"(b[0]), "r"(b[1]));
}

// ---------------------------------------------------------------------------
// Kernel 1: per-chunk M_c = phiK^T @ V  (64x64), z_c = sum_t phiK  (64)
// grid = NCHUNKS, block = 256
// ---------------------------------------------------------------------------
#define SK1 72   // smem stride (72 % 32 == 8 -> conflict-free for 4rows x 8cols and 8x4 patterns used)
#define SMEM1 ((2*CC*SK1 + 256) * 4)

__global__ void __launch_bounds__(256) k1_kv(const float* __restrict__ kin,
                                             const float* __restrict__ vin) {
    extern __shared__ float sh[];
    float* sK = sh;                 // [128][72] tf32-rounded phiK
    float* sV = sh + CC * SK1;      // [128][72] tf32-rounded V
    float* sZ = sh + 2 * CC * SK1;  // [256] z partials (fp32, unrounded)

    int g = blockIdx.x;
    int bh = g >> 6, c = g & 63;
    int b = bh >> 4, h = bh & 15;
    int t0 = c * CC;
    int tid = threadIdx.x;
    int d = tid & 63, rg = tid >> 6;

    const size_t rowstride = (size_t)HH * DD;
    size_t base = ((size_t)b * TT + t0) * rowstride + (size_t)h * DD + d;

    float zacc = 0.f;
#pragma unroll 8
    for (int p = 0; p < 32; ++p) {
        int t = p * 4 + rg;
        size_t a = base + (size_t)t * rowstride;
        float pk = phi_f(kin[a]);
        zacc += pk;                       // fp32 z (unrounded)
        sK[t * SK1 + d] = tf32r(pk);
        sV[t * SK1 + d] = tf32r(vin[a]);
    }
    sZ[tid] = zacc;
    __syncthreads();
    if (tid < 64)
        g_z[(size_t)g * 64 + tid] = sZ[tid] + sZ[tid + 64] + sZ[tid + 128] + sZ[tid + 192];

    // M[d][e] = sum_t phiK[t][d] * V[t][e] : m=d(64), n=e(64), k=t(128)
    int w = tid >> 5, lane = tid & 31;
    int gid = lane >> 2, tig = lane & 3;
    int m0 = (w & 3) * 16;
    int e0 = (w >> 2) * 32;

    float acc[4][4];
#pragma unroll
    for (int i = 0; i < 4; i++)
#pragma unroll
        for (int j = 0; j < 4; j++) acc[i][j] = 0.f;

#pragma unroll
    for (int kk = 0; kk < 16; ++kk) {
        int kb = kk * 8;
        uint32_t a[4];
        // A[m][k] = phiK[t=k][d=m]
        a[0] = __float_as_uint(sK[(kb + tig) * SK1 + m0 + gid]);
        a[1] = __float_as_uint(sK[(kb + tig) * SK1 + m0 + gid + 8]);
        a[2] = __float_as_uint(sK[(kb + tig + 4) * SK1 + m0 + gid]);
        a[3] = __float_as_uint(sK[(kb + tig + 4) * SK1 + m0 + gid + 8]);
#pragma unroll
        for (int nt = 0; nt < 4; ++nt) {
            int n0 = e0 + nt * 8;
            uint32_t bf[2];
            bf[0] = __float_as_uint(sV[(kb + tig) * SK1 + n0 + gid]);
            bf[1] = __float_as_uint(sV[(kb + tig + 4) * SK1 + n0 + gid]);
            mma8(acc[nt], a, bf);
        }
    }

    float* Mout = g_M + (size_t)g * DD * DD;
#pragma unroll
    for (int nt = 0; nt < 4; ++nt) {
        int c0 = e0 + nt * 8 + 2 * tig;
        int r0 = m0 + gid;
        *(float2*)(Mout + (size_t)r0 * DD + c0) = make_float2(acc[nt][0], acc[nt][1]);
        *(float2*)(Mout + (size_t)(r0 + 8) * DD + c0) = make_float2(acc[nt][2], acc[nt][3]);
    }
}

// ---------------------------------------------------------------------------
// Kernel 2: in-place exclusive prefix over chunks (elementwise -> parallel)
// grid = BHN*SPLIT, block = 256; each CTA owns 512 of the 4096 S-elements.
// ---------------------------------------------------------------------------
#define SPLIT 8

__global__ void __launch_bounds__(256) k2_scan() {
    int bh = blockIdx.x / SPLIT;
    int seg = blockIdx.x % SPLIT;
    int tid = threadIdx.x;
    size_t eb = (size_t)seg * 512 + tid;

    float run0 = 0.f, run1 = 0.f, zrun = 0.f;
    bool doz = (seg == 0) && (tid < 64);
    size_t mbase = (size_t)bh * 64 * 4096;
    size_t zbase = (size_t)bh * 64 * 64;

    for (int c = 0; c < 64; ++c) {
        float* p = g_M + mbase + (size_t)c * 4096 + eb;
        float a0 = p[0];
        float a1 = p[256];
        p[0] = run0;
        p[256] = run1;
        run0 += a0;
        run1 += a1;
        if (doz) {
            float* pz = g_z + zbase + (size_t)c * 64 + tid;
            float tz = *pz;
            *pz = zrun;
            zrun += tz;
        }
    }
}

// ---------------------------------------------------------------------------
// Kernel 3: per-chunk output
//  A = phiQ @ phiK^T (masked), num = A@V + phiQ@Sprev, den = rowsum(A)+phiQ.zprev+eps
// grid = NCHUNKS, block = 256 (8 warps; warp w owns rows [16w, 16w+16) )
// ---------------------------------------------------------------------------
#define SQ3 68    // 68 % 32 == 4 : conflict-free for 8rows x 4cols pattern
#define SV3 72    // 72 % 32 == 8 : conflict-free for 4rows x 8cols pattern
#define SA3 132   // 132 % 32 == 4
#define SMEM3 ((CC*SQ3 + CC*SQ3 + CC*SV3 + 64*SV3 + CC*SA3 + 128 + 64) * 4)

__global__ void __launch_bounds__(256) k3_out(const float* __restrict__ qin,
                                              const float* __restrict__ kin,
                                              const float* __restrict__ vin,
                                              float* __restrict__ out) {
    extern __shared__ float sh[];
    float* sQ = sh;                     // [128][68]
    float* sK = sQ + CC * SQ3;          // [128][68]
    float* sV = sK + CC * SQ3;          // [128][72]
    float* sS = sV + CC * SV3;          // [64][72]
    float* sA = sS + 64 * SV3;          // [128][132]
    float* sDen = sA + CC * SA3;        // [128]
    float* sZ = sDen + 128;             // [64]

    int g = blockIdx.x;
    int bh = g >> 6, c = g & 63;
    int b = bh >> 4, h = bh & 15;
    int t0 = c * CC;
    int tid = threadIdx.x;
    int d = tid & 63, rg = tid >> 6;

    const size_t rowstride = (size_t)HH * DD;
    size_t base = ((size_t)b * TT + t0) * rowstride + (size_t)h * DD + d;

#pragma unroll 8
    for (int p = 0; p < 32; ++p) {
        int t = p * 4 + rg;
        size_t a = base + (size_t)t * rowstride;
        sQ[t * SQ3 + d] = tf32r(phi_f(qin[a]));
        sK[t * SQ3 + d] = tf32r(phi_f(kin[a]));
        sV[t * SV3 + d] = tf32r(vin[a]);
    }
    {
        const float* Sp = g_M + (size_t)g * 4096;
        for (int i = tid; i < 4096; i += 256) {
            int r = i >> 6, cc2 = i & 63;
            sS[r * SV3 + cc2] = tf32r(Sp[i]);
        }
        if (tid < 64) sZ[tid] = g_z[(size_t)g * 64 + tid];
    }
    __syncthreads();

    int w = tid >> 5, lane = tid & 31;
    int gid = lane >> 2, tig = lane & 3;
    int m0 = w * 16;
    int r_lo = m0 + gid, r_hi = r_lo + 8;

    // ---- GEMM 1: A[16 x 128] = phiQ[m0:m0+16][:] @ phiK^T ----
    float accA[16][4];
#pragma unroll
    for (int i = 0; i < 16; i++)
#pragma unroll
        for (int j = 0; j < 4; j++) accA[i][j] = 0.f;

    uint32_t afr[8][4];
#pragma unroll
    for (int kk = 0; kk < 8; ++kk) {
        int kb = kk * 8;
        afr[kk][0] = __float_as_uint(sQ[r_lo * SQ3 + kb + tig]);
        afr[kk][1] = __float_as_uint(sQ[r_hi * SQ3 + kb + tig]);
        afr[kk][2] = __float_as_uint(sQ[r_lo * SQ3 + kb + tig + 4]);
        afr[kk][3] = __float_as_uint(sQ[r_hi * SQ3 + kb + tig + 4]);
    }
#pragma unroll
    for (int nt = 0; nt < 16; ++nt) {
        int n0 = nt * 8;
#pragma unroll
        for (int kk = 0; kk < 8; ++kk) {
            int kb = kk * 8;
            uint32_t bf[2];
            // B[k=d][n=s] = phiK[s][d]
            bf[0] = __float_as_uint(sK[(n0 + gid) * SQ3 + kb + tig]);
            bf[1] = __float_as_uint(sK[(n0 + gid) * SQ3 + kb + tig + 4]);
            mma8(accA[nt], afr[kk], bf);
        }
    }

    // ---- mask (s <= t), rowsum (fp32), store A to smem (tf32) ----
    float rs_lo = 0.f, rs_hi = 0.f;
#pragma unroll
    for (int nt = 0; nt < 16; ++nt) {
        int c0 = nt * 8 + 2 * tig;
        float a0 = (c0 <= r_lo) ? accA[nt][0] : 0.f;
        float a1 = (c0 + 1 <= r_lo) ? accA[nt][1] : 0.f;
        float a2 = (c0 <= r_hi) ? accA[nt][2] : 0.f;
        float a3 = (c0 + 1 <= r_hi) ? accA[nt][3] : 0.f;
        rs_lo += a0 + a1;
        rs_hi += a2 + a3;
        *(float2*)(sA + r_lo * SA3 + c0) = make_float2(tf32r(a0), tf32r(a1));
        *(float2*)(sA + r_hi * SA3 + c0) = make_float2(tf32r(a2), tf32r(a3));
    }
    rs_lo += __shfl_xor_sync(0xffffffffu, rs_lo, 1);
    rs_lo += __shfl_xor_sync(0xffffffffu, rs_lo, 2);
    rs_hi += __shfl_xor_sync(0xffffffffu, rs_hi, 1);
    rs_hi += __shfl_xor_sync(0xffffffffu, rs_hi, 2);
    if (tig == 0) {
        sDen[r_lo] = rs_lo;
        sDen[r_hi] = rs_hi;
    }
    __syncthreads();

    // ---- finalize den: + phiQ . z_prev + eps ----
    if (tid < 128) {
        float qz = 0.f;
#pragma unroll 8
        for (int dd2 = 0; dd2 < 64; ++dd2) qz += sQ[tid * SQ3 + dd2] * sZ[dd2];
        sDen[tid] = sDen[tid] + qz + EPSV;
    }
    __syncthreads();

    // ---- GEMM 2: num = phiQ @ Sprev (k=64)  +  A @ V (k up to causal bound) ----
    float acc[8][4];
#pragma unroll
    for (int i = 0; i < 8; i++)
#pragma unroll
        for (int j = 0; j < 4; j++) acc[i][j] = 0.f;

#pragma unroll
    for (int kk = 0; kk < 8; ++kk) {
        int kb = kk * 8;
        uint32_t a[4];
        a[0] = __float_as_uint(sQ[r_lo * SQ3 + kb + tig]);
        a[1] = __float_as_uint(sQ[r_hi * SQ3 + kb + tig]);
        a[2] = __float_as_uint(sQ[r_lo * SQ3 + kb + tig + 4]);
        a[3] = __float_as_uint(sQ[r_hi * SQ3 + kb + tig + 4]);
#pragma unroll
        for (int nt = 0; nt < 8; ++nt) {
            int n0 = nt * 8;
            uint32_t bf[2];
            bf[0] = __float_as_uint(sS[(kb + tig) * SV3 + n0 + gid]);
            bf[1] = __float_as_uint(sS[(kb + tig + 4) * SV3 + n0 + gid]);
            mma8(acc[nt], a, bf);
        }
    }
    int kmax = 2 * w + 2;  // cols > 16w+15 are masked out for this warp's rows
    for (int kk = 0; kk < kmax; ++kk) {
        int kb = kk * 8;
        uint32_t a[4];
        a[0] = __float_as_uint(sA[r_lo * SA3 + kb + tig]);
        a[1] = __float_as_uint(sA[r_hi * SA3 + kb + tig]);
        a[2] = __float_as_uint(sA[r_lo * SA3 + kb + tig + 4]);
        a[3] = __float_as_uint(sA[r_hi * SA3 + kb + tig + 4]);
#pragma unroll
        for (int nt = 0; nt < 8; ++nt) {
            int n0 = nt * 8;
            uint32_t bf[2];
            bf[0] = __float_as_uint(sV[(kb + tig) * SV3 + n0 + gid]);
            bf[1] = __float_as_uint(sV[(kb + tig + 4) * SV3 + n0 + gid]);
            mma8(acc[nt], a, bf);
        }
    }

    // ---- epilogue: out = num / den ----
    float inv_lo = 1.f / sDen[r_lo];
    float inv_hi = 1.f / sDen[r_hi];
    size_t obase = ((size_t)b * TT + t0) * rowstride + (size_t)h * DD;
#pragma unroll
    for (int nt = 0; nt < 8; ++nt) {
        int c0 = nt * 8 + 2 * tig;
        *(float2*)(out + obase + (size_t)r_lo * rowstride + c0) =
            make_float2(acc[nt][0] * inv_lo, acc[nt][1] * inv_lo);
        *(float2*)(out + obase + (size_t)r_hi * rowstride + c0) =
            make_float2(acc[nt][2] * inv_hi, acc[nt][3] * inv_hi);
    }
}

// ---------------------------------------------------------------------------
extern "C" void kernel_launch(void* const* d_in, const int* in_sizes, int n_in,
                              void* d_out, int out_size) {
    const float* q = (const float*)d_in[0];
    const float* k = (const float*)d_in[1];
    const float* v = (const float*)d_in[2];
    float* out = (float*)d_out;

    cudaFuncSetAttribute(k1_kv, cudaFuncAttributeMaxDynamicSharedMemorySize, SMEM1);
    cudaFuncSetAttribute(k3_out, cudaFuncAttributeMaxDynamicSharedMemorySize, SMEM3);

    k1_kv<<<NCHUNKS, 256, SMEM1>>>(k, v);
    k2_scan<<<BHN * SPLIT, 256>>>();
    k3_out<<<NCHUNKS, 256, SMEM3>>>(q, k, v, out);
}

// round 6
// speedup vs baseline: 2.4002x; 2.4002x over previous
#include <cuda_runtime.h>
#include <cstdint>
#include <math.h>

// Problem constants
#define BB 4
#define TT 8192
#define HH 16
#define DD 64
#define CC 128                 // chunk length
#define NC (TT/CC)             // 64 chunks per sequence
#define BHN (BB*HH)            // 64 (b,h) pairs
#define NCHUNKS (BHN*NC)       // 4096 total chunks
#define EPSV 1e-6f

// Scratch: per-chunk KV matrices (converted in-place to exclusive prefix = S_prev)
__device__ float g_M[(size_t)NCHUNKS * DD * DD];   // 64 MB
__device__ float g_z[(size_t)NCHUNKS * DD];        // 1 MB

__device__ __forceinline__ float phi_f(float x) {
    return x > 0.f ? x + 1.f : expf(x);   // elu(x)+1
}

__device__ __forceinline__ float tf32r(float x) {
    uint32_t u;
    asm("cvt.rna.tf32.f32 %0, %1;" : "=r"(u) : "f"(x));
    return __uint_as_float(u);
}

__device__ __forceinline__ void mma8(float* d, const uint32_t* a, const uint32_t* b) {
    asm volatile(
        "mma.sync.aligned.m16n8k8.row.col.f32.tf32.tf32.f32 "
        "{%0,%1,%2,%3}, {%4,%5,%6,%7}, {%8,%9}, {%0,%1,%2,%3};"
        : "+f"(d[0]), "+f"(d[1]), "+f"(d[2]), "+f"(d[3])
        : "r"(a[0]), "r"(a[1]), "r"(a[2]), "r"(a[3]), "r"(b[0]), "r"(b[1]));
}

// ---------------------------------------------------------------------------
// Kernel 1: per-chunk M_c = phiK^T @ V  (64x64), z_c = sum_t phiK  (64)
// grid = NCHUNKS, block = 256
// ---------------------------------------------------------------------------
#define SK1 72
#define SMEM1 ((2*CC*SK1 + 256) * 4)

__global__ void __launch_bounds__(256) k1_kv(const float* __restrict__ kin,
                                             const float* __restrict__ vin) {
    extern __shared__ float sh[];
    float* sK = sh;
    float* sV = sh + CC * SK1;
    float* sZ = sh + 2 * CC * SK1;

    int g = blockIdx.x;
    int bh = g >> 6, c = g & 63;
    int b = bh >> 4, h = bh & 15;
    int t0 = c * CC;
    int tid = threadIdx.x;
    int d = tid & 63, rg = tid >> 6;

    const size_t rowstride = (size_t)HH * DD;
    size_t base = ((size_t)b * TT + t0) * rowstride + (size_t)h * DD + d;

    float zacc = 0.f;
#pragma unroll 8
    for (int p = 0; p < 32; ++p) {
        int t = p * 4 + rg;
        size_t a = base + (size_t)t * rowstride;
        float pk = phi_f(kin[a]);
        zacc += pk;
        sK[t * SK1 + d] = tf32r(pk);
        sV[t * SK1 + d] = tf32r(vin[a]);
    }
    sZ[tid] = zacc;
    __syncthreads();
    if (tid < 64)
        g_z[(size_t)g * 64 + tid] = sZ[tid] + sZ[tid + 64] + sZ[tid + 128] + sZ[tid + 192];

    int w = tid >> 5, lane = tid & 31;
    int gid = lane >> 2, tig = lane & 3;
    int m0 = (w & 3) * 16;
    int e0 = (w >> 2) * 32;

    float acc[4][4];
#pragma unroll
    for (int i = 0; i < 4; i++)
#pragma unroll
        for (int j = 0; j < 4; j++) acc[i][j] = 0.f;

#pragma unroll
    for (int kk = 0; kk < 16; ++kk) {
        int kb = kk * 8;
        uint32_t a[4];
        a[0] = __float_as_uint(sK[(kb + tig) * SK1 + m0 + gid]);
        a[1] = __float_as_uint(sK[(kb + tig) * SK1 + m0 + gid + 8]);
        a[2] = __float_as_uint(sK[(kb + tig + 4) * SK1 + m0 + gid]);
        a[3] = __float_as_uint(sK[(kb + tig + 4) * SK1 + m0 + gid + 8]);
#pragma unroll
        for (int nt = 0; nt < 4; ++nt) {
            int n0 = e0 + nt * 8;
            uint32_t bf[2];
            bf[0] = __float_as_uint(sV[(kb + tig) * SK1 + n0 + gid]);
            bf[1] = __float_as_uint(sV[(kb + tig + 4) * SK1 + n0 + gid]);
            mma8(acc[nt], a, bf);
        }
    }

    float* Mout = g_M + (size_t)g * DD * DD;
#pragma unroll
    for (int nt = 0; nt < 4; ++nt) {
        int c0 = e0 + nt * 8 + 2 * tig;
        int r0 = m0 + gid;
        *(float2*)(Mout + (size_t)r0 * DD + c0) = make_float2(acc[nt][0], acc[nt][1]);
        *(float2*)(Mout + (size_t)(r0 + 8) * DD + c0) = make_float2(acc[nt][2], acc[nt][3]);
    }
}

// ---------------------------------------------------------------------------
// Kernel 2: exclusive prefix over chunks, fully parallel loads (MLP ~64)
// grid = BHN*16, block = 256; each thread owns ONE of the 4096 S-elements.
// ---------------------------------------------------------------------------
__global__ void __launch_bounds__(256) k2_scan() {
    int bh = blockIdx.x >> 4;
    int seg = blockIdx.x & 15;
    int e = seg * 256 + threadIdx.x;
    size_t base = (size_t)bh * 64 * 4096 + e;

    float vals[64];
#pragma unroll
    for (int c = 0; c < 64; ++c) vals[c] = g_M[base + (size_t)c * 4096];

    float run = 0.f;
#pragma unroll
    for (int c = 0; c < 64; ++c) {
        float t = vals[c];
        vals[c] = run;
        run += t;
    }
#pragma unroll
    for (int c = 0; c < 64; ++c) g_M[base + (size_t)c * 4096] = vals[c];
}

// z scan: grid = BHN, block = 64
__global__ void __launch_bounds__(64) k2_scanz() {
    int bh = blockIdx.x;
    size_t base = (size_t)bh * 64 * 64 + threadIdx.x;

    float vals[64];
#pragma unroll
    for (int c = 0; c < 64; ++c) vals[c] = g_z[base + (size_t)c * 64];
    float run = 0.f;
#pragma unroll
    for (int c = 0; c < 64; ++c) {
        float t = vals[c];
        vals[c] = run;
        run += t;
    }
#pragma unroll
    for (int c = 0; c < 64; ++c) g_z[base + (size_t)c * 64] = vals[c];
}

// ---------------------------------------------------------------------------
// Kernel 3: per-chunk output, warp-specialized, 512 threads.
//   warps 0-7 : A = mask(phiQ@phiK^T) -> sA (+rowsum), then upper half of A@V
//   warps 8-15: phiQ@Sprev + phiQ.z, then lower half of A@V, write sOut
//   epilogue  : out = (accA + sOut) / den
// grid = NCHUNKS
// ---------------------------------------------------------------------------
#define SQ3 68    // 68 % 32 == 4 : conflict-free (gid*4+tig)
#define SV3 72    // 72 % 32 == 8 : conflict-free (tig*8+gid)
#define SA3 132   // 132 % 32 == 4
#define SO3 72    // float2 epilogue pattern (8*gid+2*tig) conflict-free

#define SQ_OFF  0
#define SKk_OFF (SQ_OFF + CC*SQ3)
#define SVv_OFF (SKk_OFF + CC*SQ3)
#define SS_OFF  (SVv_OFF + CC*SV3)
#define SA_OFF  (SS_OFF + 64*SV3)
#define SO_OFF  (SA_OFF + CC*SA3)
#define SRS_OFF (SO_OFF + CC*SO3)
#define SQZ_OFF (SRS_OFF + 128)
#define SZ_OFF  (SQZ_OFF + 128)
#define SMEM3_FLOATS (SZ_OFF + 64)
#define SMEM3 (SMEM3_FLOATS * 4)

__global__ void __launch_bounds__(512, 1) k3_out(const float* __restrict__ qin,
                                                 const float* __restrict__ kin,
                                                 const float* __restrict__ vin,
                                                 float* __restrict__ out) {
    extern __shared__ float sh[];
    float* sQ = sh + SQ_OFF;     // [128][68] tf32 phiQ
    float* sK = sh + SKk_OFF;    // [128][68] tf32 phiK
    float* sV = sh + SVv_OFF;    // [128][72] tf32 V
    float* sS = sh + SS_OFF;     // [64][72]  tf32 S_prev
    float* sA = sh + SA_OFF;     // [128][132] tf32 masked A
    float* sO = sh + SO_OFF;     // [128][72] fp32 partial num (Q@S + half A@V)
    float* sRs = sh + SRS_OFF;   // [128] rowsum(A)
    float* sQz = sh + SQZ_OFF;   // [128] phiQ . z_prev
    float* sZ = sh + SZ_OFF;     // [64]

    int g = blockIdx.x;
    int bh = g >> 6, c = g & 63;
    int b = bh >> 4, h = bh & 15;
    int t0 = c * CC;
    int tid = threadIdx.x;

    const size_t rowstride = (size_t)HH * DD;

    // ---- load phase (all 512 threads) ----
    {
        int d = tid & 63, rg = tid >> 6;  // rg 0..7
        size_t base = ((size_t)b * TT + t0) * rowstride + (size_t)h * DD + d;
#pragma unroll 4
        for (int p = 0; p < 16; ++p) {
            int t = p * 8 + rg;
            size_t a = base + (size_t)t * rowstride;
            sQ[t * SQ3 + d] = tf32r(phi_f(qin[a]));
            sK[t * SQ3 + d] = tf32r(phi_f(kin[a]));
            sV[t * SV3 + d] = tf32r(vin[a]);
        }
        const float* Sp = g_M + (size_t)g * 4096;
        for (int i = tid; i < 4096; i += 512)
            sS[(i >> 6) * SV3 + (i & 63)] = tf32r(Sp[i]);
        if (tid < 64) sZ[tid] = g_z[(size_t)g * 64 + tid];
    }
    __syncthreads();

    int wid = tid >> 5, lane = tid & 31;
    int gid = lane >> 2, tig = lane & 3;
    bool grpA = (wid < 8);
    int w = grpA ? wid : (wid - 8);      // row-tile index 0..7 in both groups
    int m0 = w * 16;
    int r_lo = m0 + gid, r_hi = r_lo + 8;
    int kmax = 2 * w + 2;                // causal tile count for this row band
    int khalf = w + 1;                   // split point of A@V k-tiles

    float acc[8][4];
#pragma unroll
    for (int i = 0; i < 8; i++)
#pragma unroll
        for (int j = 0; j < 4; j++) acc[i][j] = 0.f;

    if (grpA) {
        // ---- phase 1: masked A = phiQ @ phiK^T, streamed per 8-col tile ----
        uint32_t afr[8][4];
#pragma unroll
        for (int kk = 0; kk < 8; ++kk) {
            int kb = kk * 8;
            afr[kk][0] = __float_as_uint(sQ[r_lo * SQ3 + kb + tig]);
            afr[kk][1] = __float_as_uint(sQ[r_hi * SQ3 + kb + tig]);
            afr[kk][2] = __float_as_uint(sQ[r_lo * SQ3 + kb + tig + 4]);
            afr[kk][3] = __float_as_uint(sQ[r_hi * SQ3 + kb + tig + 4]);
        }
        float rs_lo = 0.f, rs_hi = 0.f;
#pragma unroll 2
        for (int nt = 0; nt < kmax; ++nt) {
            int n0 = nt * 8;
            float p0[4] = {0.f, 0.f, 0.f, 0.f};
            float p1[4] = {0.f, 0.f, 0.f, 0.f};
#pragma unroll
            for (int kk = 0; kk < 4; ++kk) {
                int kb = kk * 8;
                uint32_t bf[2];
                bf[0] = __float_as_uint(sK[(n0 + gid) * SQ3 + kb + tig]);
                bf[1] = __float_as_uint(sK[(n0 + gid) * SQ3 + kb + tig + 4]);
                mma8(p0, afr[kk], bf);
            }
#pragma unroll
            for (int kk = 4; kk < 8; ++kk) {
                int kb = kk * 8;
                uint32_t bf[2];
                bf[0] = __float_as_uint(sK[(n0 + gid) * SQ3 + kb + tig]);
                bf[1] = __float_as_uint(sK[(n0 + gid) * SQ3 + kb + tig + 4]);
                mma8(p1, afr[kk], bf);
            }
            int c0 = n0 + 2 * tig;
            float a0 = (c0 <= r_lo) ? (p0[0] + p1[0]) : 0.f;
            float a1 = (c0 + 1 <= r_lo) ? (p0[1] + p1[1]) : 0.f;
            float a2 = (c0 <= r_hi) ? (p0[2] + p1[2]) : 0.f;
            float a3 = (c0 + 1 <= r_hi) ? (p0[3] + p1[3]) : 0.f;
            rs_lo += a0 + a1;
            rs_hi += a2 + a3;
            *(float2*)(sA + r_lo * SA3 + c0) = make_float2(tf32r(a0), tf32r(a1));
            *(float2*)(sA + r_hi * SA3 + c0) = make_float2(tf32r(a2), tf32r(a3));
        }
        rs_lo += __shfl_xor_sync(0xffffffffu, rs_lo, 1);
        rs_lo += __shfl_xor_sync(0xffffffffu, rs_lo, 2);
        rs_hi += __shfl_xor_sync(0xffffffffu, rs_hi, 1);
        rs_hi += __shfl_xor_sync(0xffffffffu, rs_hi, 2);
        if (tig == 0) {
            sRs[r_lo] = rs_lo;
            sRs[r_hi] = rs_hi;
        }
    } else {
        // ---- phase 1: num_inter = phiQ @ Sprev ; qz = phiQ . z_prev ----
#pragma unroll
        for (int kk = 0; kk < 8; ++kk) {
            int kb = kk * 8;
            uint32_t a[4];
            a[0] = __float_as_uint(sQ[r_lo * SQ3 + kb + tig]);
            a[1] = __float_as_uint(sQ[r_hi * SQ3 + kb + tig]);
            a[2] = __float_as_uint(sQ[r_lo * SQ3 + kb + tig + 4]);
            a[3] = __float_as_uint(sQ[r_hi * SQ3 + kb + tig + 4]);
#pragma unroll
            for (int nt = 0; nt < 8; ++nt) {
                int n0 = nt * 8;
                uint32_t bf[2];
                bf[0] = __float_as_uint(sS[(kb + tig) * SV3 + n0 + gid]);
                bf[1] = __float_as_uint(sS[(kb + tig + 4) * SV3 + n0 + gid]);
                mma8(acc[nt], a, bf);
            }
        }
        float qlo = 0.f, qhi = 0.f;
#pragma unroll
        for (int dd = 0; dd < 16; ++dd) {
            int d2 = tig * 16 + dd;
            float zv = sZ[d2];
            qlo += sQ[r_lo * SQ3 + d2] * zv;
            qhi += sQ[r_hi * SQ3 + d2] * zv;
        }
        qlo += __shfl_xor_sync(0xffffffffu, qlo, 1);
        qlo += __shfl_xor_sync(0xffffffffu, qlo, 2);
        qhi += __shfl_xor_sync(0xffffffffu, qhi, 1);
        qhi += __shfl_xor_sync(0xffffffffu, qhi, 2);
        if (tig == 0) {
            sQz[r_lo] = qlo;
            sQz[r_hi] = qhi;
        }
    }
    __syncthreads();   // sA (and sRs/sQz) visible to both groups

    // ---- phase 2: A@V split between the paired warps ----
    {
        int kbeg = grpA ? khalf : 0;
        int kend = grpA ? kmax : khalf;
#pragma unroll 2
        for (int kk2 = kbeg; kk2 < kend; ++kk2) {
            int kb = kk2 * 8;
            uint32_t a[4];
            a[0] = __float_as_uint(sA[r_lo * SA3 + kb + tig]);
            a[1] = __float_as_uint(sA[r_hi * SA3 + kb + tig]);
            a[2] = __float_as_uint(sA[r_lo * SA3 + kb + tig + 4]);
            a[3] = __float_as_uint(sA[r_hi * SA3 + kb + tig + 4]);
#pragma unroll
            for (int nt = 0; nt < 8; ++nt) {
                int n0 = nt * 8;
                uint32_t bf[2];
                bf[0] = __float_as_uint(sV[(kb + tig) * SV3 + n0 + gid]);
                bf[1] = __float_as_uint(sV[(kb + tig + 4) * SV3 + n0 + gid]);
                mma8(acc[nt], a, bf);
            }
        }
    }
    if (!grpA) {
        // group B deposits its partial numerator (Q@S + lower-half A@V)
#pragma unroll
        for (int nt = 0; nt < 8; ++nt) {
            int c0 = nt * 8 + 2 * tig;
            *(float2*)(sO + r_lo * SO3 + c0) = make_float2(acc[nt][0], acc[nt][1]);
            *(float2*)(sO + r_hi * SO3 + c0) = make_float2(acc[nt][2], acc[nt][3]);
        }
    }
    __syncthreads();

    // ---- epilogue (group A): out = (acc + sO) / den ----
    if (grpA) {
        float inv_lo = 1.f / (sRs[r_lo] + sQz[r_lo] + EPSV);
        float inv_hi = 1.f / (sRs[r_hi] + sQz[r_hi] + EPSV);
        size_t obase = ((size_t)b * TT + t0) * rowstride + (size_t)h * DD;
#pragma unroll
        for (int nt = 0; nt < 8; ++nt) {
            int c0 = nt * 8 + 2 * tig;
            float2 o_lo = *(float2*)(sO + r_lo * SO3 + c0);
            float2 o_hi = *(float2*)(sO + r_hi * SO3 + c0);
            *(float2*)(out + obase + (size_t)r_lo * rowstride + c0) =
                make_float2((acc[nt][0] + o_lo.x) * inv_lo, (acc[nt][1] + o_lo.y) * inv_lo);
            *(float2*)(out + obase + (size_t)r_hi * rowstride + c0) =
                make_float2((acc[nt][2] + o_hi.x) * inv_hi, (acc[nt][3] + o_hi.y) * inv_hi);
        }
    }
}

// ---------------------------------------------------------------------------
extern "C" void kernel_launch(void* const* d_in, const int* in_sizes, int n_in,
                              void* d_out, int out_size) {
    const float* q = (const float*)d_in[0];
    const float* k = (const float*)d_in[1];
    const float* v = (const float*)d_in[2];
    float* out = (float*)d_out;

    cudaFuncSetAttribute(k1_kv, cudaFuncAttributeMaxDynamicSharedMemorySize, SMEM1);
    cudaFuncSetAttribute(k3_out, cudaFuncAttributeMaxDynamicSharedMemorySize, SMEM3);

    k1_kv<<<NCHUNKS, 256, SMEM1>>>(k, v);
    k2_scan<<<BHN * 16, 256>>>();
    k2_scanz<<<BHN, 64>>>();
    k3_out<<<NCHUNKS, 512, SMEM3>>>(q, k, v, out);
}

// round 7
// speedup vs baseline: 2.4771x; 1.0320x over previous
#include <cuda_runtime.h>
#include <cstdint>
#include <math.h>

// Problem constants
#define BB 4
#define TT 8192
#define HH 16
#define DD 64
#define CC 128                 // chunk length
#define NC (TT/CC)             // 64 chunks per sequence
#define BHN (BB*HH)            // 64 (b,h) pairs
#define NCHUNKS (BHN*NC)       // 4096 total chunks
#define EPSV 1e-6f

// Scratch: per-chunk KV matrices (converted in-place to exclusive prefix = S_prev)
__device__ float g_M[(size_t)NCHUNKS * DD * DD];   // 64 MB
__device__ float g_z[(size_t)NCHUNKS * DD];        // 1 MB

__device__ __forceinline__ float phi_f(float x) {
    return x > 0.f ? x + 1.f : expf(x);   // elu(x)+1
}

__device__ __forceinline__ float tf32r(float x) {
    uint32_t u;
    asm("cvt.rna.tf32.f32 %0, %1;" : "=r"(u) : "f"(x));
    return __uint_as_float(u);
}

__device__ __forceinline__ void mma8(float* d, const uint32_t* a, const uint32_t* b) {
    asm volatile(
        "mma.sync.aligned.m16n8k8.row.col.f32.tf32.tf32.f32 "
        "{%0,%1,%2,%3}, {%4,%5,%6,%7}, {%8,%9}, {%0,%1,%2,%3};"
        : "+f"(d[0]), "+f"(d[1]), "+f"(d[2]), "+f"(d[3])
        : "r"(a[0]), "r"(a[1]), "r"(a[2]), "r"(a[3]), "r"(b[0]), "r"(b[1]));
}

// ---------------------------------------------------------------------------
// Kernel 1: per-chunk M_c = phiK^T @ V  (64x64), z_c = sum_t phiK  (64)
// grid = NCHUNKS, block = 256
// ---------------------------------------------------------------------------
#define SK1 72
#define SMEM1 ((2*CC*SK1 + 256) * 4)

__global__ void __launch_bounds__(256) k1_kv(const float* __restrict__ kin,
                                             const float* __restrict__ vin) {
    extern __shared__ float sh[];
    float* sK = sh;
    float* sV = sh + CC * SK1;
    float* sZ = sh + 2 * CC * SK1;

    int g = blockIdx.x;
    int bh = g >> 6, c = g & 63;
    int b = bh >> 4, h = bh & 15;
    int t0 = c * CC;
    int tid = threadIdx.x;
    int d = tid & 63, rg = tid >> 6;

    const size_t rowstride = (size_t)HH * DD;
    size_t base = ((size_t)b * TT + t0) * rowstride + (size_t)h * DD + d;

    float zacc = 0.f;
#pragma unroll 8
    for (int p = 0; p < 32; ++p) {
        int t = p * 4 + rg;
        size_t a = base + (size_t)t * rowstride;
        float pk = phi_f(kin[a]);
        zacc += pk;
        sK[t * SK1 + d] = tf32r(pk);
        sV[t * SK1 + d] = tf32r(vin[a]);
    }
    sZ[tid] = zacc;
    __syncthreads();
    if (tid < 64)
        g_z[(size_t)g * 64 + tid] = sZ[tid] + sZ[tid + 64] + sZ[tid + 128] + sZ[tid + 192];

    int w = tid >> 5, lane = tid & 31;
    int gid = lane >> 2, tig = lane & 3;
    int m0 = (w & 3) * 16;
    int e0 = (w >> 2) * 32;

    float acc[4][4];
#pragma unroll
    for (int i = 0; i < 4; i++)
#pragma unroll
        for (int j = 0; j < 4; j++) acc[i][j] = 0.f;

#pragma unroll
    for (int kk = 0; kk < 16; ++kk) {
        int kb = kk * 8;
        uint32_t a[4];
        a[0] = __float_as_uint(sK[(kb + tig) * SK1 + m0 + gid]);
        a[1] = __float_as_uint(sK[(kb + tig) * SK1 + m0 + gid + 8]);
        a[2] = __float_as_uint(sK[(kb + tig + 4) * SK1 + m0 + gid]);
        a[3] = __float_as_uint(sK[(kb + tig + 4) * SK1 + m0 + gid + 8]);
#pragma unroll
        for (int nt = 0; nt < 4; ++nt) {
            int n0 = e0 + nt * 8;
            uint32_t bf[2];
            bf[0] = __float_as_uint(sV[(kb + tig) * SK1 + n0 + gid]);
            bf[1] = __float_as_uint(sV[(kb + tig + 4) * SK1 + n0 + gid]);
            mma8(acc[nt], a, bf);
        }
    }

    float* Mout = g_M + (size_t)g * DD * DD;
#pragma unroll
    for (int nt = 0; nt < 4; ++nt) {
        int c0 = e0 + nt * 8 + 2 * tig;
        int r0 = m0 + gid;
        *(float2*)(Mout + (size_t)r0 * DD + c0) = make_float2(acc[nt][0], acc[nt][1]);
        *(float2*)(Mout + (size_t)(r0 + 8) * DD + c0) = make_float2(acc[nt][2], acc[nt][3]);
    }
}

// ---------------------------------------------------------------------------
// Kernel 2: exclusive prefix over chunks, fully parallel loads
// ---------------------------------------------------------------------------
__global__ void __launch_bounds__(256) k2_scan() {
    int bh = blockIdx.x >> 4;
    int seg = blockIdx.x & 15;
    int e = seg * 256 + threadIdx.x;
    size_t base = (size_t)bh * 64 * 4096 + e;

    float vals[64];
#pragma unroll
    for (int c = 0; c < 64; ++c) vals[c] = g_M[base + (size_t)c * 4096];

    float run = 0.f;
#pragma unroll
    for (int c = 0; c < 64; ++c) {
        float t = vals[c];
        vals[c] = run;
        run += t;
    }
#pragma unroll
    for (int c = 0; c < 64; ++c) g_M[base + (size_t)c * 4096] = vals[c];
}

__global__ void __launch_bounds__(64) k2_scanz() {
    int bh = blockIdx.x;
    size_t base = (size_t)bh * 64 * 64 + threadIdx.x;

    float vals[64];
#pragma unroll
    for (int c = 0; c < 64; ++c) vals[c] = g_z[base + (size_t)c * 64];
    float run = 0.f;
#pragma unroll
    for (int c = 0; c < 64; ++c) {
        float t = vals[c];
        vals[c] = run;
        run += t;
    }
#pragma unroll
    for (int c = 0; c < 64; ++c) g_z[base + (size_t)c * 64] = vals[c];
}

// ---------------------------------------------------------------------------
// Kernel 3: per-chunk output, 512 threads, band-swapped balanced schedule.
//   Warp pair p = (warp p, warp p+8):
//     phase 1: produce masked A for band p  (A-warp ktiles [0,p+1),
//              B-warp ktiles [p+1,2p+2)), partial rowsums to sRsA/sRsB;
//              Q@S_prev for band 7-p (A-warp cols 0-31, B-warp cols 32-63);
//              A-warp also computes qz for band 7-p.
//     phase 2: A@V for band 7-p (each warp its own 32 cols, all ktiles).
//     epilogue: each warp writes its 16 rows x 32 cols of band 7-p.
//   Every warp issues exactly 104 mma8.
// grid = NCHUNKS
// ---------------------------------------------------------------------------
#define SQ3 68    // 68 % 32 == 4 : conflict-free (gid*4+tig)
#define SV3 72    // 72 % 32 == 8 : conflict-free (tig*8+gid)
#define SA3 132   // 132 % 32 == 4

#define SQ_OFF   0
#define SKk_OFF  (SQ_OFF + CC*SQ3)
#define SVv_OFF  (SKk_OFF + CC*SQ3)
#define SS_OFF   (SVv_OFF + CC*SV3)
#define SA_OFF   (SS_OFF + 64*SV3)
#define SRSA_OFF (SA_OFF + CC*SA3)
#define SRSB_OFF (SRSA_OFF + 128)
#define SQZ_OFF  (SRSB_OFF + 128)
#define SZ_OFF   (SQZ_OFF + 128)
#define SMEM3_FLOATS (SZ_OFF + 64)
#define SMEM3 (SMEM3_FLOATS * 4)

__global__ void __launch_bounds__(512, 1) k3_out(const float* __restrict__ qin,
                                                 const float* __restrict__ kin,
                                                 const float* __restrict__ vin,
                                                 float* __restrict__ out) {
    extern __shared__ float sh[];
    float* sQ = sh + SQ_OFF;      // [128][68] tf32 phiQ
    float* sK = sh + SKk_OFF;     // [128][68] tf32 phiK
    float* sV = sh + SVv_OFF;     // [128][72] tf32 V
    float* sS = sh + SS_OFF;      // [64][72]  tf32 S_prev
    float* sA = sh + SA_OFF;      // [128][132] tf32 masked A
    float* sRsA = sh + SRSA_OFF;  // [128] rowsum partial (A-warps)
    float* sRsB = sh + SRSB_OFF;  // [128] rowsum partial (B-warps)
    float* sQz = sh + SQZ_OFF;    // [128] phiQ . z_prev
    float* sZ = sh + SZ_OFF;      // [64]

    int g = blockIdx.x;
    int bh = g >> 6, c = g & 63;
    int b = bh >> 4, h = bh & 15;
    int t0 = c * CC;
    int tid = threadIdx.x;

    const size_t rowstride = (size_t)HH * DD;

    // ---- load phase (all 512 threads) ----
    {
        int d = tid & 63, rg = tid >> 6;  // rg 0..7
        size_t base = ((size_t)b * TT + t0) * rowstride + (size_t)h * DD + d;
#pragma unroll 4
        for (int pp = 0; pp < 16; ++pp) {
            int t = pp * 8 + rg;
            size_t a = base + (size_t)t * rowstride;
            sQ[t * SQ3 + d] = tf32r(phi_f(qin[a]));
            sK[t * SQ3 + d] = tf32r(phi_f(kin[a]));
            sV[t * SV3 + d] = tf32r(vin[a]);
        }
        const float* Sp = g_M + (size_t)g * 4096;
        for (int i = tid; i < 4096; i += 512)
            sS[(i >> 6) * SV3 + (i & 63)] = tf32r(Sp[i]);
        if (tid < 64) sZ[tid] = g_z[(size_t)g * 64 + tid];
    }
    __syncthreads();

    int wid = tid >> 5, lane = tid & 31;
    int gid = lane >> 2, tig = lane & 3;
    bool isA = (wid < 8);
    int p = wid & 7;             // pair index
    int bo = 7 - p;              // output band for this pair
    int rq_lo = p * 16 + gid, rq_hi = rq_lo + 8;    // QK band rows
    int ro_lo = bo * 16 + gid, ro_hi = ro_lo + 8;   // output band rows
    int ntbase = isA ? 0 : 4;    // this warp's 4 n-tiles (32 output cols)

    // ---- phase 1a: masked A for band p, split ktiles within pair ----
    {
        uint32_t afr[8][4];
#pragma unroll
        for (int kk = 0; kk < 8; ++kk) {
            int kb = kk * 8;
            afr[kk][0] = __float_as_uint(sQ[rq_lo * SQ3 + kb + tig]);
            afr[kk][1] = __float_as_uint(sQ[rq_hi * SQ3 + kb + tig]);
            afr[kk][2] = __float_as_uint(sQ[rq_lo * SQ3 + kb + tig + 4]);
            afr[kk][3] = __float_as_uint(sQ[rq_hi * SQ3 + kb + tig + 4]);
        }
        int nt0 = isA ? 0 : (p + 1);
        int nt1 = isA ? (p + 1) : (2 * p + 2);
        float rs_lo = 0.f, rs_hi = 0.f;
#pragma unroll 2
        for (int nt = nt0; nt < nt1; ++nt) {
            int n0 = nt * 8;
            float p0[4] = {0.f, 0.f, 0.f, 0.f};
            float p1[4] = {0.f, 0.f, 0.f, 0.f};
#pragma unroll
            for (int kk = 0; kk < 4; ++kk) {
                int kb = kk * 8;
                uint32_t bf[2];
                bf[0] = __float_as_uint(sK[(n0 + gid) * SQ3 + kb + tig]);
                bf[1] = __float_as_uint(sK[(n0 + gid) * SQ3 + kb + tig + 4]);
                mma8(p0, afr[kk], bf);
            }
#pragma unroll
            for (int kk = 4; kk < 8; ++kk) {
                int kb = kk * 8;
                uint32_t bf[2];
                bf[0] = __float_as_uint(sK[(n0 + gid) * SQ3 + kb + tig]);
                bf[1] = __float_as_uint(sK[(n0 + gid) * SQ3 + kb + tig + 4]);
                mma8(p1, afr[kk], bf);
            }
            int c0 = n0 + 2 * tig;
            float a0 = (c0 <= rq_lo) ? (p0[0] + p1[0]) : 0.f;
            float a1 = (c0 + 1 <= rq_lo) ? (p0[1] + p1[1]) : 0.f;
            float a2 = (c0 <= rq_hi) ? (p0[2] + p1[2]) : 0.f;
            float a3 = (c0 + 1 <= rq_hi) ? (p0[3] + p1[3]) : 0.f;
            rs_lo += a0 + a1;
            rs_hi += a2 + a3;
            *(float2*)(sA + rq_lo * SA3 + c0) = make_float2(tf32r(a0), tf32r(a1));
            *(float2*)(sA + rq_hi * SA3 + c0) = make_float2(tf32r(a2), tf32r(a3));
        }
        rs_lo += __shfl_xor_sync(0xffffffffu, rs_lo, 1);
        rs_lo += __shfl_xor_sync(0xffffffffu, rs_lo, 2);
        rs_hi += __shfl_xor_sync(0xffffffffu, rs_hi, 1);
        rs_hi += __shfl_xor_sync(0xffffffffu, rs_hi, 2);
        float* rsArr = isA ? sRsA : sRsB;
        if (tig == 0) {
            rsArr[rq_lo] = rs_lo;
            rsArr[rq_hi] = rs_hi;
        }
    }

    // ---- phase 1b: qz for band bo (A-warps only) ----
    if (isA) {
        float qlo = 0.f, qhi = 0.f;
#pragma unroll
        for (int dd = 0; dd < 16; ++dd) {
            int d2 = tig * 16 + dd;
            float zv = sZ[d2];
            qlo += sQ[ro_lo * SQ3 + d2] * zv;
            qhi += sQ[ro_hi * SQ3 + d2] * zv;
        }
        qlo += __shfl_xor_sync(0xffffffffu, qlo, 1);
        qlo += __shfl_xor_sync(0xffffffffu, qlo, 2);
        qhi += __shfl_xor_sync(0xffffffffu, qhi, 1);
        qhi += __shfl_xor_sync(0xffffffffu, qhi, 2);
        if (tig == 0) {
            sQz[ro_lo] = qlo;
            sQz[ro_hi] = qhi;
        }
    }

    // ---- phase 1c: Q@S_prev for band bo, own 4 n-tiles ----
    float acc[4][4];
#pragma unroll
    for (int i = 0; i < 4; i++)
#pragma unroll
        for (int j = 0; j < 4; j++) acc[i][j] = 0.f;

#pragma unroll
    for (int kk = 0; kk < 8; ++kk) {
        int kb = kk * 8;
        uint32_t a[4];
        a[0] = __float_as_uint(sQ[ro_lo * SQ3 + kb + tig]);
        a[1] = __float_as_uint(sQ[ro_hi * SQ3 + kb + tig]);
        a[2] = __float_as_uint(sQ[ro_lo * SQ3 + kb + tig + 4]);
        a[3] = __float_as_uint(sQ[ro_hi * SQ3 + kb + tig + 4]);
#pragma unroll
        for (int nt2 = 0; nt2 < 4; ++nt2) {
            int n0 = (ntbase + nt2) * 8;
            uint32_t bf[2];
            bf[0] = __float_as_uint(sS[(kb + tig) * SV3 + n0 + gid]);
            bf[1] = __float_as_uint(sS[(kb + tig + 4) * SV3 + n0 + gid]);
            mma8(acc[nt2], a, bf);
        }
    }
    __syncthreads();   // sA (band bo, written by pair 7-p), sRs*, sQz visible

    // ---- phase 2: A@V for band bo, all causal ktiles, own 4 n-tiles ----
    {
        int ktAV = 2 * bo + 2;
#pragma unroll 2
        for (int kt = 0; kt < ktAV; ++kt) {
            int kb = kt * 8;
            uint32_t a[4];
            a[0] = __float_as_uint(sA[ro_lo * SA3 + kb + tig]);
            a[1] = __float_as_uint(sA[ro_hi * SA3 + kb + tig]);
            a[2] = __float_as_uint(sA[ro_lo * SA3 + kb + tig + 4]);
            a[3] = __float_as_uint(sA[ro_hi * SA3 + kb + tig + 4]);
#pragma unroll
            for (int nt2 = 0; nt2 < 4; ++nt2) {
                int n0 = (ntbase + nt2) * 8;
                uint32_t bf[2];
                bf[0] = __float_as_uint(sV[(kb + tig) * SV3 + n0 + gid]);
                bf[1] = __float_as_uint(sV[(kb + tig + 4) * SV3 + n0 + gid]);
                mma8(acc[nt2], a, bf);
            }
        }
    }

    // ---- epilogue: each warp writes its 16 rows x 32 cols of band bo ----
    {
        float inv_lo = 1.f / (sRsA[ro_lo] + sRsB[ro_lo] + sQz[ro_lo] + EPSV);
        float inv_hi = 1.f / (sRsA[ro_hi] + sRsB[ro_hi] + sQz[ro_hi] + EPSV);
        size_t obase = ((size_t)b * TT + t0) * rowstride + (size_t)h * DD;
#pragma unroll
        for (int nt2 = 0; nt2 < 4; ++nt2) {
            int c0 = (ntbase + nt2) * 8 + 2 * tig;
            *(float2*)(out + obase + (size_t)ro_lo * rowstride + c0) =
                make_float2(acc[nt2][0] * inv_lo, acc[nt2][1] * inv_lo);
            *(float2*)(out + obase + (size_t)ro_hi * rowstride + c0) =
                make_float2(acc[nt2][2] * inv_hi, acc[nt2][3] * inv_hi);
        }
    }
}

// ---------------------------------------------------------------------------
extern "C" void kernel_launch(void* const* d_in, const int* in_sizes, int n_in,
                              void* d_out, int out_size) {
    const float* q = (const float*)d_in[0];
    const float* k = (const float*)d_in[1];
    const float* v = (const float*)d_in[2];
    float* out = (float*)d_out;

    cudaFuncSetAttribute(k1_kv, cudaFuncAttributeMaxDynamicSharedMemorySize, SMEM1);
    cudaFuncSetAttribute(k3_out, cudaFuncAttributeMaxDynamicSharedMemorySize, SMEM3);

    k1_kv<<<NCHUNKS, 256, SMEM1>>>(k, v);
    k2_scan<<<BHN * 16, 256>>>();
    k2_scanz<<<BHN, 64>>>();
    k3_out<<<NCHUNKS, 512, SMEM3>>>(q, k, v, out);
}

// round 11
// speedup vs baseline: 5.0011x; 2.0189x over previous
#include <cuda_runtime.h>
#include <cuda_fp16.h>
#include <cstdint>
#include <math.h>

// Problem constants
#define BB 4
#define TT 8192
#define HH 16
#define DD 64
#define CC 128                 // chunk length
#define NC (TT/CC)             // 64 chunks per sequence
#define BHN (BB*HH)            // 64 (b,h) pairs
#define NCHUNKS (BHN*NC)       // 4096 total chunks
#define EPSV 1e-6f

// Scratch: per-chunk KV matrices (converted in-place to exclusive prefix = S_prev)
__device__ float g_M[(size_t)NCHUNKS * DD * DD];   // 64 MB
__device__ float g_z[(size_t)NCHUNKS * DD];        // 1 MB

__device__ __forceinline__ float phi_f(float x) {
    return x > 0.f ? x + 1.f : expf(x);   // elu(x)+1
}

__device__ __forceinline__ void mma16(float* d, const uint32_t* a, const uint32_t* b) {
    asm volatile(
        "mma.sync.aligned.m16n8k16.row.col.f32.f16.f16.f32 "
        "{%0,%1,%2,%3}, {%4,%5,%6,%7}, {%8,%9}, {%0,%1,%2,%3};"
        : "+f"(d[0]), "+f"(d[1]), "+f"(d[2]), "+f"(d[3])
        : "r"(a[0]), "r"(a[1]), "r"(a[2]), "r"(a[3]), "r"(b[0]), "r"(b[1]));
}

__device__ __forceinline__ uint32_t ldh2(const __half* p) {
    return *(const uint32_t*)p;   // 4B-aligned half2 load
}
__device__ __forceinline__ uint32_t packh2(float lo, float hi) {
    __half2 h = __floats2half2_rn(lo, hi);
    return *(uint32_t*)&h;
}

// ---------------------------------------------------------------------------
// Kernel 1 (fp16): per-chunk M_c = phiK^T @ V (64x64), z_c = sum_t phiK (64)
// grid = NCHUNKS, block = 256.  sKT/sVT stored transposed: [feat][t].
// ---------------------------------------------------------------------------
#define K1S 136   // halfs per row; 136/2=68 banks == 4 mod 32 -> 4*gid+tig conflict-free
#define SMEM1 (2*64*K1S*2 + 256*4)

__global__ void __launch_bounds__(256, 4) k1_kv(const float* __restrict__ kin,
                                                const float* __restrict__ vin) {
    extern __shared__ __align__(16) char smraw[];
    __half* sKT = (__half*)smraw;              // [64 d][136] phiK^T
    __half* sVT = sKT + 64 * K1S;              // [64 e][136] V^T
    float* sZ = (float*)(sVT + 64 * K1S);      // [256]

    int g = blockIdx.x;
    int bh = g >> 6, c = g & 63;
    int b = bh >> 4, h = bh & 15;
    int t0 = c * CC;
    int tid = threadIdx.x;
    int d = tid & 63, rg = tid >> 6;

    const size_t rowstride = (size_t)HH * DD;
    size_t base = ((size_t)b * TT + t0) * rowstride + (size_t)h * DD + d;

    float zacc = 0.f;
#pragma unroll 8
    for (int p = 0; p < 32; ++p) {
        int t = p * 4 + rg;
        size_t a = base + (size_t)t * rowstride;
        float pk = phi_f(kin[a]);
        zacc += pk;                               // fp32 z, unrounded
        sKT[d * K1S + t] = __float2half_rn(pk);
        sVT[d * K1S + t] = __float2half_rn(vin[a]);
    }
    sZ[tid] = zacc;
    __syncthreads();
    if (tid < 64)
        g_z[(size_t)g * 64 + tid] = sZ[tid] + sZ[tid + 64] + sZ[tid + 128] + sZ[tid + 192];

    int w = tid >> 5, lane = tid & 31;
    int gid = lane >> 2, tig = lane & 3;
    int m0 = (w & 3) * 16;          // d-band
    int e0 = (w >> 2) * 32;         // e-half

    float acc[4][4];
#pragma unroll
    for (int i = 0; i < 4; i++)
#pragma unroll
        for (int j = 0; j < 4; j++) acc[i][j] = 0.f;

#pragma unroll
    for (int ks = 0; ks < 8; ++ks) {
        int kb = ks * 16;
        const __half* ar = sKT + (m0 + gid) * K1S + kb + 2 * tig;
        uint32_t a[4];
        a[0] = ldh2(ar);
        a[1] = ldh2(ar + 8 * K1S);
        a[2] = ldh2(ar + 8);
        a[3] = ldh2(ar + 8 * K1S + 8);
#pragma unroll
        for (int nt = 0; nt < 4; ++nt) {
            const __half* br = sVT + (e0 + nt * 8 + gid) * K1S + kb + 2 * tig;
            uint32_t bf[2] = { ldh2(br), ldh2(br + 8) };
            mma16(acc[nt], a, bf);
        }
    }

    float* Mout = g_M + (size_t)g * DD * DD;
#pragma unroll
    for (int nt = 0; nt < 4; ++nt) {
        int c0 = e0 + nt * 8 + 2 * tig;
        int r0 = m0 + gid;
        *(float2*)(Mout + (size_t)r0 * DD + c0) = make_float2(acc[nt][0], acc[nt][1]);
        *(float2*)(Mout + (size_t)(r0 + 8) * DD + c0) = make_float2(acc[nt][2], acc[nt][3]);
    }
}

// ---------------------------------------------------------------------------
// Kernel 2: exclusive prefix over chunks, fully parallel loads
// ---------------------------------------------------------------------------
__global__ void __launch_bounds__(256) k2_scan() {
    int bh = blockIdx.x >> 4;
    int seg = blockIdx.x & 15;
    int e = seg * 256 + threadIdx.x;
    size_t base = (size_t)bh * 64 * 4096 + e;

    float vals[64];
#pragma unroll
    for (int c = 0; c < 64; ++c) vals[c] = g_M[base + (size_t)c * 4096];

    float run = 0.f;
#pragma unroll
    for (int c = 0; c < 64; ++c) {
        float t = vals[c];
        vals[c] = run;
        run += t;
    }
#pragma unroll
    for (int c = 0; c < 64; ++c) g_M[base + (size_t)c * 4096] = vals[c];
}

__global__ void __launch_bounds__(64) k2_scanz() {
    int bh = blockIdx.x;
    size_t base = (size_t)bh * 64 * 64 + threadIdx.x;

    float vals[64];
#pragma unroll
    for (int c = 0; c < 64; ++c) vals[c] = g_z[base + (size_t)c * 64];
    float run = 0.f;
#pragma unroll
    for (int c = 0; c < 64; ++c) {
        float t = vals[c];
        vals[c] = run;
        run += t;
    }
#pragma unroll
    for (int c = 0; c < 64; ++c) g_z[base + (size_t)c * 64] = vals[c];
}

// ---------------------------------------------------------------------------
// Kernel 3 (fp16, register-A): per-chunk output. 256 threads, 8 warps.
//   Warp owns band bo (rows 16*bo..16*bo+15), bo = wid<4 ? wid : 11-wid
//   (pairs warps so each SMSP gets exactly 208 MMAs).
//   1) acc_out = phiQ @ S_prev (m16n8k16, fp32 acc)
//   2) qz = phiQ . z_prev
//   3) for j=0..bo: A-tile (16x16) = mask(phiQ@phiK^T) -> fp32, rowsum,
//      convert acc->a-fragment IN REGISTERS (layout-exact), acc_out += A@V
//   4) out = acc_out / (rowsum + qz + eps)
// No sA, one __syncthreads. smem ~62 KB -> 3 CTAs/SM.
// ---------------------------------------------------------------------------
#define SQS 72    // 36 banks == 4 mod 32
#define SVS 136   // 68 banks == 4 mod 32
#define SSS 72

#define H_SQ   0
#define H_SK   (H_SQ + 128*SQS)      // 9216
#define H_SVT  (H_SK + 128*SQS)      // 18432
#define H_SST  (H_SVT + 64*SVS)      // 27136
#define H_END  (H_SST + 64*SSS)      // 31744 halfs
#define SMEM3  (H_END*2 + 64*4 + 16)

__global__ void __launch_bounds__(256, 3) k3_out(const float* __restrict__ qin,
                                                 const float* __restrict__ kin,
                                                 const float* __restrict__ vin,
                                                 float* __restrict__ out) {
    extern __shared__ __align__(16) char smraw[];
    __half* sQ  = (__half*)smraw + H_SQ;    // [128 t][72]  phiQ (row-major t,d)
    __half* sK  = (__half*)smraw + H_SK;    // [128 s][72]  phiK (row-major s,d)
    __half* sVT = (__half*)smraw + H_SVT;   // [64 e][136]  V^T (e rows, t cols)
    __half* sST = (__half*)smraw + H_SST;   // [64 e][72]   S_prev^T (e rows, d cols)
    float* sZ = (float*)((__half*)smraw + H_END);  // [64]

    int g = blockIdx.x;
    int bh = g >> 6, c = g & 63;
    int b = bh >> 4, h = bh & 15;
    int t0 = c * CC;
    int tid = threadIdx.x;

    const size_t rowstride = (size_t)HH * DD;

    // ---- load phase ----
    {
        int d = tid & 63, rg = tid >> 6;
        size_t base = ((size_t)b * TT + t0) * rowstride + (size_t)h * DD + d;
#pragma unroll 8
        for (int p = 0; p < 32; ++p) {
            int t = p * 4 + rg;
            size_t a = base + (size_t)t * rowstride;
            sQ[t * SQS + d] = __float2half_rn(phi_f(qin[a]));
            sK[t * SQS + d] = __float2half_rn(phi_f(kin[a]));
            sVT[d * SVS + t] = __float2half_rn(vin[a]);
        }
        const float* Sp = g_M + (size_t)g * 4096;
#pragma unroll
        for (int i = tid; i < 4096; i += 256)
            sST[(i & 63) * SSS + (i >> 6)] = __float2half_rn(Sp[i]);
        if (tid < 64) sZ[tid] = g_z[(size_t)g * 64 + tid];
    }
    __syncthreads();

    int wid = tid >> 5, lane = tid & 31;
    int gid = lane >> 2, tig = lane & 3;
    int bo = (wid < 4) ? wid : (11 - wid);   // SMSP-balanced band assignment
    int r_lo = bo * 16 + gid, r_hi = r_lo + 8;

    float acc[8][4];
#pragma unroll
    for (int i = 0; i < 8; i++)
#pragma unroll
        for (int j = 0; j < 4; j++) acc[i][j] = 0.f;

    // ---- phase 1: acc = phiQ @ S_prev  (k = d, 4 k16-steps) ----
#pragma unroll
    for (int ks = 0; ks < 4; ++ks) {
        int kb = ks * 16;
        const __half* ar = sQ + r_lo * SQS + kb + 2 * tig;
        uint32_t a[4];
        a[0] = ldh2(ar);
        a[1] = ldh2(ar + 8 * SQS);
        a[2] = ldh2(ar + 8);
        a[3] = ldh2(ar + 8 * SQS + 8);
#pragma unroll
        for (int nt = 0; nt < 8; ++nt) {
            const __half* br = sST + (nt * 8 + gid) * SSS + kb + 2 * tig;
            uint32_t bf[2] = { ldh2(br), ldh2(br + 8) };
            mma16(acc[nt], a, bf);
        }
    }

    // ---- phase 2: qz = phiQ . z_prev ----
    float qlo = 0.f, qhi = 0.f;
#pragma unroll
    for (int dd = 0; dd < 16; ++dd) {
        int d2 = tig * 16 + dd;
        float zv = sZ[d2];
        qlo += __half2float(sQ[r_lo * SQS + d2]) * zv;
        qhi += __half2float(sQ[r_hi * SQS + d2]) * zv;
    }
    qlo += __shfl_xor_sync(0xffffffffu, qlo, 1);
    qlo += __shfl_xor_sync(0xffffffffu, qlo, 2);
    qhi += __shfl_xor_sync(0xffffffffu, qhi, 1);
    qhi += __shfl_xor_sync(0xffffffffu, qhi, 2);

    // ---- phase 3: per 16-col k-tile: QK -> mask -> pack -> A@V ----
    float rs_lo = 0.f, rs_hi = 0.f;
#pragma unroll 2
    for (int j = 0; j <= bo; ++j) {
        float acc8[2][4];
#pragma unroll
        for (int u = 0; u < 2; ++u)
#pragma unroll
            for (int i = 0; i < 4; ++i) acc8[u][i] = 0.f;

#pragma unroll
        for (int ks = 0; ks < 4; ++ks) {
            int kb = ks * 16;
            const __half* ar = sQ + r_lo * SQS + kb + 2 * tig;
            uint32_t a[4];
            a[0] = ldh2(ar);
            a[1] = ldh2(ar + 8 * SQS);
            a[2] = ldh2(ar + 8);
            a[3] = ldh2(ar + 8 * SQS + 8);
#pragma unroll
            for (int u = 0; u < 2; ++u) {
                const __half* br = sK + (16 * j + 8 * u + gid) * SQS + kb + 2 * tig;
                uint32_t bf[2] = { ldh2(br), ldh2(br + 8) };
                mma16(acc8[u], a, bf);
            }
        }

        // mask (col <= row), rowsum, pack acc -> a-fragment (layout-exact)
        int cb0 = 16 * j + 2 * tig;
        int cb1 = cb0 + 8;
        float A00 = (cb0     <= r_lo) ? acc8[0][0] : 0.f;
        float A01 = (cb0 + 1 <= r_lo) ? acc8[0][1] : 0.f;
        float A02 = (cb0     <= r_hi) ? acc8[0][2] : 0.f;
        float A03 = (cb0 + 1 <= r_hi) ? acc8[0][3] : 0.f;
        float A10 = (cb1     <= r_lo) ? acc8[1][0] : 0.f;
        float A11 = (cb1 + 1 <= r_lo) ? acc8[1][1] : 0.f;
        float A12 = (cb1     <= r_hi) ? acc8[1][2] : 0.f;
        float A13 = (cb1 + 1 <= r_hi) ? acc8[1][3] : 0.f;
        rs_lo += A00 + A01 + A10 + A11;
        rs_hi += A02 + A03 + A12 + A13;
        uint32_t aA[4];
        aA[0] = packh2(A00, A01);
        aA[1] = packh2(A02, A03);
        aA[2] = packh2(A10, A11);
        aA[3] = packh2(A12, A13);

        // A@V: k16-range = s in [16j, 16j+16)
#pragma unroll
        for (int nt = 0; nt < 8; ++nt) {
            const __half* br = sVT + (nt * 8 + gid) * SVS + 16 * j + 2 * tig;
            uint32_t bf[2] = { ldh2(br), ldh2(br + 8) };
            mma16(acc[nt], aA, bf);
        }
    }

    rs_lo += __shfl_xor_sync(0xffffffffu, rs_lo, 1);
    rs_lo += __shfl_xor_sync(0xffffffffu, rs_lo, 2);
    rs_hi += __shfl_xor_sync(0xffffffffu, rs_hi, 1);
    rs_hi += __shfl_xor_sync(0xffffffffu, rs_hi, 2);

    // ---- epilogue ----
    float inv_lo = 1.f / (rs_lo + qlo + EPSV);
    float inv_hi = 1.f / (rs_hi + qhi + EPSV);
    size_t obase = ((size_t)b * TT + t0) * rowstride + (size_t)h * DD;
#pragma unroll
    for (int nt = 0; nt < 8; ++nt) {
        int c0 = nt * 8 + 2 * tig;
        *(float2*)(out + obase + (size_t)r_lo * rowstride + c0) =
            make_float2(acc[nt][0] * inv_lo, acc[nt][1] * inv_lo);
        *(float2*)(out + obase + (size_t)r_hi * rowstride + c0) =
            make_float2(acc[nt][2] * inv_hi, acc[nt][3] * inv_hi);
    }
}

// ---------------------------------------------------------------------------
extern "C" void kernel_launch(void* const* d_in, const int* in_sizes, int n_in,
                              void* d_out, int out_size) {
    const float* q = (const float*)d_in[0];
    const float* k = (const float*)d_in[1];
    const float* v = (const float*)d_in[2];
    float* out = (float*)d_out;

    cudaFuncSetAttribute(k1_kv, cudaFuncAttributeMaxDynamicSharedMemorySize, SMEM1);
    cudaFuncSetAttribute(k3_out, cudaFuncAttributeMaxDynamicSharedMemorySize, SMEM3);

    k1_kv<<<NCHUNKS, 256, SMEM1>>>(k, v);
    k2_scan<<<BHN * 16, 256>>>();
    k2_scanz<<<BHN, 64>>>();
    k3_out<<<NCHUNKS, 256, SMEM3>>>(q, k, v, out);
}

// round 12
// speedup vs baseline: 5.3828x; 1.0763x over previous
#include <cuda_runtime.h>
#include <cuda_fp16.h>
#include <cstdint>
#include <math.h>

// Problem constants
#define BB 4
#define TT 8192
#define HH 16
#define DD 64
#define CC 128                 // chunk length
#define NC (TT/CC)             // 64 chunks per sequence
#define BHN (BB*HH)            // 64 (b,h) pairs
#define NCHUNKS (BHN*NC)       // 4096 total chunks
#define EPSV 1e-6f

// Scratch (fp16): per-chunk M^T (e-major), converted in-place to exclusive prefix S_prev^T
__device__ __half g_M16[(size_t)NCHUNKS * DD * DD];   // 32 MB
__device__ float  g_z[(size_t)NCHUNKS * DD];          // 1 MB (fp32)

__device__ __forceinline__ float phi_f(float x) {
    return x > 0.f ? x + 1.f : expf(x);   // elu(x)+1
}

__device__ __forceinline__ void mma16(float* d, const uint32_t* a, const uint32_t* b) {
    asm volatile(
        "mma.sync.aligned.m16n8k16.row.col.f32.f16.f16.f32 "
        "{%0,%1,%2,%3}, {%4,%5,%6,%7}, {%8,%9}, {%0,%1,%2,%3};"
        : "+f"(d[0]), "+f"(d[1]), "+f"(d[2]), "+f"(d[3])
        : "r"(a[0]), "r"(a[1]), "r"(a[2]), "r"(a[3]), "r"(b[0]), "r"(b[1]));
}

__device__ __forceinline__ uint32_t ldh2(const __half* p) {
    return *(const uint32_t*)p;
}
__device__ __forceinline__ uint32_t packh2(float lo, float hi) {
    __half2 h = __floats2half2_rn(lo, hi);
    return *(uint32_t*)&h;
}
__device__ __forceinline__ uint32_t sm32(const void* p) {
    return (uint32_t)__cvta_generic_to_shared(p);
}
__device__ __forceinline__ void ldsm4(uint32_t* r, uint32_t a) {
    asm volatile("ldmatrix.sync.aligned.m8n8.x4.shared.b16 {%0,%1,%2,%3}, [%4];"
                 : "=r"(r[0]), "=r"(r[1]), "=r"(r[2]), "=r"(r[3]) : "r"(a));
}

// ---------------------------------------------------------------------------
// Kernel 1 (fp16): per-chunk M^T[e][d] = sum_t V[t][e] phiK[t][d],
//                  z_c = sum_t phiK.  grid = NCHUNKS, block = 256.
// (A operand = V^T rows, B operand = phiK^T rows -> acc indexed [e][d],
//  so gmem write of M^T is d-contiguous.)
// ---------------------------------------------------------------------------
#define K1S 136   // halfs per row
#define SMEM1 (2*64*K1S*2 + 256*4)

__global__ void __launch_bounds__(256, 4) k1_kv(const float* __restrict__ kin,
                                                const float* __restrict__ vin) {
    extern __shared__ __align__(16) char smraw[];
    __half* sKT = (__half*)smraw;              // [64 d][136] phiK^T
    __half* sVT = sKT + 64 * K1S;              // [64 e][136] V^T
    float* sZ = (float*)(sVT + 64 * K1S);      // [256]

    int g = blockIdx.x;
    int bh = g >> 6, c = g & 63;
    int b = bh >> 4, h = bh & 15;
    int t0 = c * CC;
    int tid = threadIdx.x;
    int d = tid & 63, rg = tid >> 6;

    const size_t rowstride = (size_t)HH * DD;
    size_t base = ((size_t)b * TT + t0) * rowstride + (size_t)h * DD + d;

    float zacc = 0.f;
#pragma unroll 8
    for (int p = 0; p < 32; ++p) {
        int t = p * 4 + rg;
        size_t a = base + (size_t)t * rowstride;
        float pk = phi_f(kin[a]);
        zacc += pk;                               // fp32 z, unrounded
        sKT[d * K1S + t] = __float2half_rn(pk);
        sVT[d * K1S + t] = __float2half_rn(vin[a]);
    }
    sZ[tid] = zacc;
    __syncthreads();
    if (tid < 64)
        g_z[(size_t)g * 64 + tid] = sZ[tid] + sZ[tid + 64] + sZ[tid + 128] + sZ[tid + 192];

    int w = tid >> 5, lane = tid & 31;
    int gid = lane >> 2, tig = lane & 3;
    int m0 = (w & 3) * 16;          // e-band (rows of M^T)
    int d0 = (w >> 2) * 32;         // d-half (cols of M^T)

    float acc[4][4];
#pragma unroll
    for (int i = 0; i < 4; i++)
#pragma unroll
        for (int j = 0; j < 4; j++) acc[i][j] = 0.f;

#pragma unroll
    for (int ks = 0; ks < 8; ++ks) {
        int kb = ks * 16;
        const __half* ar = sVT + (m0 + gid) * K1S + kb + 2 * tig;
        uint32_t a[4];
        a[0] = ldh2(ar);
        a[1] = ldh2(ar + 8 * K1S);
        a[2] = ldh2(ar + 8);
        a[3] = ldh2(ar + 8 * K1S + 8);
#pragma unroll
        for (int nt = 0; nt < 4; ++nt) {
            const __half* br = sKT + (d0 + nt * 8 + gid) * K1S + kb + 2 * tig;
            uint32_t bf[2] = { ldh2(br), ldh2(br + 8) };
            mma16(acc[nt], a, bf);
        }
    }

    __half* Mout = g_M16 + (size_t)g * DD * DD;   // [e][d]
#pragma unroll
    for (int nt = 0; nt < 4; ++nt) {
        int c0 = d0 + nt * 8 + 2 * tig;
        int r0 = m0 + gid;
        *(uint32_t*)(Mout + (size_t)r0 * DD + c0) = packh2(acc[nt][0], acc[nt][1]);
        *(uint32_t*)(Mout + (size_t)(r0 + 8) * DD + c0) = packh2(acc[nt][2], acc[nt][3]);
    }
}

// ---------------------------------------------------------------------------
// Kernel 2: exclusive prefix over chunks, fp16 in/out (half2 per thread),
// fp32 running sums.  grid = BHN*8, block = 256.
// ---------------------------------------------------------------------------
__global__ void __launch_bounds__(256) k2_scan() {
    int bh = blockIdx.x >> 3;
    int seg = blockIdx.x & 7;
    int u = seg * 256 + threadIdx.x;               // uint32 index, 2048 per chunk
    uint32_t* base = (uint32_t*)g_M16 + (size_t)bh * 64 * 2048 + u;

    uint32_t vals[64];
#pragma unroll
    for (int c = 0; c < 64; ++c) vals[c] = base[(size_t)c * 2048];

    float r0 = 0.f, r1 = 0.f;
#pragma unroll
    for (int c = 0; c < 64; ++c) {
        __half2 hv = *(__half2*)&vals[c];
        float a0 = __low2float(hv), a1 = __high2float(hv);
        vals[c] = packh2(r0, r1);
        r0 += a0;
        r1 += a1;
    }
#pragma unroll
    for (int c = 0; c < 64; ++c) base[(size_t)c * 2048] = vals[c];
}

__global__ void __launch_bounds__(64) k2_scanz() {
    int bh = blockIdx.x;
    size_t base = (size_t)bh * 64 * 64 + threadIdx.x;

    float vals[64];
#pragma unroll
    for (int c = 0; c < 64; ++c) vals[c] = g_z[base + (size_t)c * 64];
    float run = 0.f;
#pragma unroll
    for (int c = 0; c < 64; ++c) {
        float t = vals[c];
        vals[c] = run;
        run += t;
    }
#pragma unroll
    for (int c = 0; c < 64; ++c) g_z[base + (size_t)c * 64] = vals[c];
}

// ---------------------------------------------------------------------------
// Kernel 3 (fp16, register-A, LDSM): 256 threads, 8 warps, warp owns band
// bo = wid<4 ? wid : 11-wid.  Q a-fragments loaded ONCE via ldmatrix.x4 and
// reused across Q@S and all causal QK tiles; all B fragments via ldmatrix.x4.
// ---------------------------------------------------------------------------
#define SQS 72    // 144B stride: 16 mod 128 -> LDSM conflict-free, 16B aligned rows
#define SVS 136   // 272B stride: 16 mod 128
#define SSS 72

#define H_SQ   0
#define H_SK   (H_SQ + 128*SQS)      // 9216
#define H_SVT  (H_SK + 128*SQS)      // 18432
#define H_SST  (H_SVT + 64*SVS)      // 27136
#define H_END  (H_SST + 64*SSS)      // 31744 halfs
#define SMEM3  (H_END*2 + 64*4 + 16)

__global__ void __launch_bounds__(256, 3) k3_out(const float* __restrict__ qin,
                                                 const float* __restrict__ kin,
                                                 const float* __restrict__ vin,
                                                 float* __restrict__ out) {
    extern __shared__ __align__(16) char smraw[];
    __half* sQ  = (__half*)smraw + H_SQ;    // [128 t][72]  phiQ
    __half* sK  = (__half*)smraw + H_SK;    // [128 s][72]  phiK
    __half* sVT = (__half*)smraw + H_SVT;   // [64 e][136]  V^T
    __half* sST = (__half*)smraw + H_SST;   // [64 e][72]   S_prev^T
    float* sZ = (float*)((__half*)smraw + H_END);  // [64]

    int g = blockIdx.x;
    int bh = g >> 6, c = g & 63;
    int b = bh >> 4, h = bh & 15;
    int t0 = c * CC;
    int tid = threadIdx.x;

    const size_t rowstride = (size_t)HH * DD;

    // ---- load phase ----
    {
        int d = tid & 63, rg = tid >> 6;
        size_t base = ((size_t)b * TT + t0) * rowstride + (size_t)h * DD + d;
#pragma unroll 8
        for (int p = 0; p < 32; ++p) {
            int t = p * 4 + rg;
            size_t a = base + (size_t)t * rowstride;
            sQ[t * SQS + d] = __float2half_rn(phi_f(qin[a]));
            sK[t * SQS + d] = __float2half_rn(phi_f(kin[a]));
            sVT[d * SVS + t] = __float2half_rn(vin[a]);
        }
        // S_prev^T is e-major in gmem (fp16): conflict-free uint32 copy
        const uint32_t* Sp = (const uint32_t*)(g_M16 + (size_t)g * 4096);
#pragma unroll
        for (int i = tid; i < 2048; i += 256) {
            int e = i >> 5, d2 = (i & 31) * 2;
            *(uint32_t*)&sST[e * SSS + d2] = Sp[i];
        }
        if (tid < 64) sZ[tid] = g_z[(size_t)g * 64 + tid];
    }
    __syncthreads();

    int wid = tid >> 5, lane = tid & 31;
    int gid = lane >> 2, tig = lane & 3;
    int bo = (wid < 4) ? wid : (11 - wid);   // SMSP-balanced band assignment
    int r_lo = bo * 16 + gid, r_hi = r_lo + 8;

    // LDSM per-thread base addresses
    int row8 = lane & 7, seg = lane >> 3;
    // A matrices: (seg&1)->rows+8, (seg&2)->k+8
    uint32_t aQbase = sm32(sQ + (bo * 16 + row8 + ((seg & 1) << 3)) * SQS + ((seg & 2) << 2));
    // B matrices: (seg&1)->k+8, (seg>>1)->n+8
    uint32_t sTbase = sm32(sST + (row8 + ((seg >> 1) << 3)) * SSS + ((seg & 1) << 3));
    uint32_t sKbase = sm32(sK + (row8 + ((seg >> 1) << 3)) * SQS + ((seg & 1) << 3));
    uint32_t sVbase = sm32(sVT + (row8 + ((seg >> 1) << 3)) * SVS + ((seg & 1) << 3));

    // ---- Q a-fragments: loaded once, reused by Q@S and all QK tiles ----
    uint32_t afr[4][4];
#pragma unroll
    for (int ks = 0; ks < 4; ++ks) ldsm4(afr[ks], aQbase + ks * 32);

    float acc[8][4];
#pragma unroll
    for (int i = 0; i < 8; i++)
#pragma unroll
        for (int j = 0; j < 4; j++) acc[i][j] = 0.f;

    // ---- phase 1: acc = phiQ @ S_prev ----
#pragma unroll
    for (int ks = 0; ks < 4; ++ks) {
#pragma unroll
        for (int ntp = 0; ntp < 4; ++ntp) {
            uint32_t bf4[4];
            ldsm4(bf4, sTbase + (uint32_t)(16 * ntp * SSS) * 2 + ks * 32);
            mma16(acc[2 * ntp], afr[ks], bf4 + 0);
            mma16(acc[2 * ntp + 1], afr[ks], bf4 + 2);
        }
    }

    // ---- phase 2: qz = phiQ . z_prev ----
    float qlo = 0.f, qhi = 0.f;
#pragma unroll
    for (int dd = 0; dd < 16; ++dd) {
        int d2 = tig * 16 + dd;
        float zv = sZ[d2];
        qlo += __half2float(sQ[r_lo * SQS + d2]) * zv;
        qhi += __half2float(sQ[r_hi * SQS + d2]) * zv;
    }
    qlo += __shfl_xor_sync(0xffffffffu, qlo, 1);
    qlo += __shfl_xor_sync(0xffffffffu, qlo, 2);
    qhi += __shfl_xor_sync(0xffffffffu, qhi, 1);
    qhi += __shfl_xor_sync(0xffffffffu, qhi, 2);

    // ---- phase 3: per 16-col k-tile: QK -> mask -> pack -> A@V ----
    float rs_lo = 0.f, rs_hi = 0.f;
#pragma unroll 2
    for (int j = 0; j <= bo; ++j) {
        float acc8[2][4];
#pragma unroll
        for (int u = 0; u < 2; ++u)
#pragma unroll
            for (int i = 0; i < 4; ++i) acc8[u][i] = 0.f;

        uint32_t jkoff = (uint32_t)(16 * j * SQS) * 2;
#pragma unroll
        for (int ks = 0; ks < 4; ++ks) {
            uint32_t bf4[4];
            ldsm4(bf4, sKbase + jkoff + ks * 32);
            mma16(acc8[0], afr[ks], bf4 + 0);
            mma16(acc8[1], afr[ks], bf4 + 2);
        }

        // mask (col <= row), rowsum, pack acc -> a-fragment (layout-exact)
        int cb0 = 16 * j + 2 * tig;
        int cb1 = cb0 + 8;
        float A00 = (cb0     <= r_lo) ? acc8[0][0] : 0.f;
        float A01 = (cb0 + 1 <= r_lo) ? acc8[0][1] : 0.f;
        float A02 = (cb0     <= r_hi) ? acc8[0][2] : 0.f;
        float A03 = (cb0 + 1 <= r_hi) ? acc8[0][3] : 0.f;
        float A10 = (cb1     <= r_lo) ? acc8[1][0] : 0.f;
        float A11 = (cb1 + 1 <= r_lo) ? acc8[1][1] : 0.f;
        float A12 = (cb1     <= r_hi) ? acc8[1][2] : 0.f;
        float A13 = (cb1 + 1 <= r_hi) ? acc8[1][3] : 0.f;
        rs_lo += A00 + A01 + A10 + A11;
        rs_hi += A02 + A03 + A12 + A13;
        uint32_t aA[4];
        aA[0] = packh2(A00, A01);
        aA[1] = packh2(A02, A03);
        aA[2] = packh2(A10, A11);
        aA[3] = packh2(A12, A13);

        // A@V: k16-range = s in [16j, 16j+16)
        uint32_t jvoff = (uint32_t)(16 * j) * 2;
#pragma unroll
        for (int ntp = 0; ntp < 4; ++ntp) {
            uint32_t bf4[4];
            ldsm4(bf4, sVbase + (uint32_t)(16 * ntp * SVS) * 2 + jvoff);
            mma16(acc[2 * ntp], aA, bf4 + 0);
            mma16(acc[2 * ntp + 1], aA, bf4 + 2);
        }
    }

    rs_lo += __shfl_xor_sync(0xffffffffu, rs_lo, 1);
    rs_lo += __shfl_xor_sync(0xffffffffu, rs_lo, 2);
    rs_hi += __shfl_xor_sync(0xffffffffu, rs_hi, 1);
    rs_hi += __shfl_xor_sync(0xffffffffu, rs_hi, 2);

    // ---- epilogue ----
    float inv_lo = 1.f / (rs_lo + qlo + EPSV);
    float inv_hi = 1.f / (rs_hi + qhi + EPSV);
    size_t obase = ((size_t)b * TT + t0) * rowstride + (size_t)h * DD;
#pragma unroll
    for (int nt = 0; nt < 8; ++nt) {
        int c0 = nt * 8 + 2 * tig;
        *(float2*)(out + obase + (size_t)r_lo * rowstride + c0) =
            make_float2(acc[nt][0] * inv_lo, acc[nt][1] * inv_lo);
        *(float2*)(out + obase + (size_t)r_hi * rowstride + c0) =
            make_float2(acc[nt][2] * inv_hi, acc[nt][3] * inv_hi);
    }
}

// ---------------------------------------------------------------------------
extern "C" void kernel_launch(void* const* d_in, const int* in_sizes, int n_in,
                              void* d_out, int out_size) {
    const float* q = (const float*)d_in[0];
    const float* k = (const float*)d_in[1];
    const float* v = (const float*)d_in[2];
    float* out = (float*)d_out;

    cudaFuncSetAttribute(k1_kv, cudaFuncAttributeMaxDynamicSharedMemorySize, SMEM1);
    cudaFuncSetAttribute(k3_out, cudaFuncAttributeMaxDynamicSharedMemorySize, SMEM3);

    k1_kv<<<NCHUNKS, 256, SMEM1>>>(k, v);
    k2_scan<<<BHN * 8, 256>>>();
    k2_scanz<<<BHN, 64>>>();
    k3_out<<<NCHUNKS, 256, SMEM3>>>(q, k, v, out);
}